// round 12
// baseline (speedup 1.0000x reference)
#include <cuda_runtime.h>
#include <math.h>

#define Hh   128
#define NPRc 3000
#define EPRc 6000
#define NTOT 48000
#define NCc  512     // C columns: [0,384) iou_x, [384,512) wf_x

// static scratch (no allocations allowed)
__device__ float g_C[(size_t)NTOT * NCc];   // 98.3 MB
__device__ float g_c[(size_t)NTOT * Hh];    // 24.6 MB
__device__ float g_Ut[256 * 512];           // U^T: [k][row]  (row<384: U_iou, else U_f)
__device__ float g_Wt[128 * 512];           // W^T: [k][row]  (row<384: W_iou, else W_f)

union F2U { float2 f; unsigned long long u; };
__device__ __forceinline__ float2 ffma2(float2 a, float2 b, float2 c) {
    F2U A, B, C2, D;
    A.f = a; B.f = b; C2.f = c;
    asm("fma.rn.f32x2 %0, %1, %2, %3;" : "=l"(D.u) : "l"(A.u), "l"(B.u), "l"(C2.u));
    return D.f;
}
__device__ __forceinline__ float2 spl(float b) { return make_float2(b, b); }
__device__ __forceinline__ float sigf(float x) { return 1.0f / (1.0f + expf(-x)); }

// ---------------------------------------------------------------------------
// One-shot weight transposes, merged (writes coalesced). grid 768.
// ---------------------------------------------------------------------------
__global__ __launch_bounds__(256) void k_trans(const float* __restrict__ U_iou,
                                               const float* __restrict__ U_f,
                                               const float* __restrict__ W_iou,
                                               const float* __restrict__ W_f) {
    int b = blockIdx.x;
    if (b < 512) {
        int idx = b * 256 + threadIdx.x;               // 131072
        int k = idx >> 9, row = idx & 511;
        g_Ut[idx] = (row < 384) ? U_iou[row * 256 + k] : U_f[(row - 384) * 256 + k];
    } else {
        int idx = (b - 512) * 256 + threadIdx.x;       // 65536
        int k = idx >> 9, row = idx & 511;
        g_Wt[idx] = (row < 384) ? W_iou[row * 128 + k] : W_f[(row - 384) * 128 + k];
    }
}

// ---------------------------------------------------------------------------
// k_pre: C[n][0:384] = x @ W_iou^T ; C[n][384:512] = x @ W_f^T
// Tiled GEMM: 32 rows x 512 cols per block, K=128. grid 1500, 2 blocks/SM.
// smem floats: A[128*36] @0 | Bs[2*8*512] @4608 | xs[32*132] @12800 = 17024
// ---------------------------------------------------------------------------
#define PRE_SMEMB (17024 * 4)

__global__ __launch_bounds__(256, 2) void k_pre(const float* __restrict__ x) {
    extern __shared__ float sm[];
    float* A  = sm;           // [k][row], stride 36
    float* Bs = sm + 4608;    // [buf][kk][512]
    float* xs = sm + 12800;   // [row][132]
    int t  = threadIdx.x;
    int r0 = blockIdx.x * 32;

#pragma unroll
    for (int j = 0; j < 4; j++) {                      // stage x coalesced
        int f = t + 256 * j, row = f >> 5, q = f & 31;
        *(float4*)&xs[row * 132 + 4 * q] = *((const float4*)(x + (size_t)(r0 + row) * 128) + q);
    }
    __syncthreads();
#pragma unroll
    for (int j = 0; j < 4; j++) {                      // transpose -> A[k][row]
        int f = t + 256 * j, row = f & 31, q = f >> 5;
        float4 v = *(const float4*)&xs[row * 132 + 4 * q];
        A[(4 * q + 0) * 36 + row] = v.x; A[(4 * q + 1) * 36 + row] = v.y;
        A[(4 * q + 2) * 36 + row] = v.z; A[(4 * q + 3) * 36 + row] = v.w;
    }
#pragma unroll
    for (int j = 0; j < 4; j++) {                      // B chunk 0 (k=0..7), coalesced
        int f = t + 256 * j, ks = f >> 7, c4 = (f & 127) * 4;
        *(float4*)&Bs[ks * 512 + c4] = *(const float4*)&g_Wt[ks * 512 + c4];
    }
    __syncthreads();

    int ct = t & 127;            // cols ct, 128+ct, 256+ct, 384+ct
    int rb = (t >> 7) * 16;      // 16 rows
    float2 acc[4][8];
#pragma unroll
    for (int cc = 0; cc < 4; cc++)
#pragma unroll
        for (int r = 0; r < 8; r++) acc[cc][r] = make_float2(0.f, 0.f);

#pragma unroll 1
    for (int c = 0; c < 16; c++) {                     // 16 chunks x 8 k
        float4 nb[4];
        if (c < 15) {
#pragma unroll
            for (int j = 0; j < 4; j++) {
                int f = t + 256 * j, ks = f >> 7, c4 = (f & 127) * 4;
                nb[j] = *(const float4*)&g_Wt[((c + 1) * 8 + ks) * 512 + c4];
            }
        }
        const float* Bb = Bs + (c & 1) * 4096;
#pragma unroll
        for (int kk = 0; kk < 8; kk++) {
            int kg = c * 8 + kk;
            float2 b0 = spl(Bb[kk * 512 + ct]);
            float2 b1 = spl(Bb[kk * 512 + 128 + ct]);
            float2 b2 = spl(Bb[kk * 512 + 256 + ct]);
            float2 b3 = spl(Bb[kk * 512 + 384 + ct]);
            const float* ap = A + kg * 36 + rb;
#pragma unroll
            for (int g4 = 0; g4 < 4; g4++) {
                float4 av = *(const float4*)(ap + 4 * g4);
                float2 p0 = make_float2(av.x, av.y), p1 = make_float2(av.z, av.w);
                acc[0][2*g4]   = ffma2(b0, p0, acc[0][2*g4]);
                acc[0][2*g4+1] = ffma2(b0, p1, acc[0][2*g4+1]);
                acc[1][2*g4]   = ffma2(b1, p0, acc[1][2*g4]);
                acc[1][2*g4+1] = ffma2(b1, p1, acc[1][2*g4+1]);
                acc[2][2*g4]   = ffma2(b2, p0, acc[2][2*g4]);
                acc[2][2*g4+1] = ffma2(b2, p1, acc[2][2*g4+1]);
                acc[3][2*g4]   = ffma2(b3, p0, acc[3][2*g4]);
                acc[3][2*g4+1] = ffma2(b3, p1, acc[3][2*g4+1]);
            }
        }
        if (c < 15) {
            float* d = Bs + ((c + 1) & 1) * 4096;
#pragma unroll
            for (int j = 0; j < 4; j++) {
                int f = t + 256 * j, ks = f >> 7, c4 = (f & 127) * 4;
                *(float4*)&d[ks * 512 + c4] = nb[j];
            }
            __syncthreads();
        }
    }
#pragma unroll
    for (int cc = 0; cc < 4; cc++) {                   // grid*32 == 48000, no guard
        int col = ct + 128 * cc;
#pragma unroll
        for (int r = 0; r < 8; r++) {
            int row = r0 + rb + 2 * r;
            g_C[(size_t)row * NCc + col]       = acc[cc][r].x;
            g_C[(size_t)(row + 1) * NCc + col] = acc[cc][r].y;
        }
    }
}

// ---------------------------------------------------------------------------
// Round 0: leaves. iou_mid = 0, c = 0.
// ---------------------------------------------------------------------------
__global__ __launch_bounds__(256) void k_round0(float* __restrict__ h,
                                                const int* __restrict__ order0,
                                                const float* __restrict__ b_iou) {
    int idx = blockIdx.x * 256 + threadIdx.x;
    if (idx >= NPRc * Hh) return;
    int j = idx >> 7, m = idx & 127;
    int node = order0[j];
    const float* Cp = g_C + (size_t)node * NCc;
    float gi = Cp[m]       + b_iou[m];
    float go = Cp[128 + m] + b_iou[128 + m];
    float gu = Cp[256 + m] + b_iou[256 + m];
    float ct = sigf(gi) * tanhf(gu);
    g_c[(size_t)node * Hh + m] = ct;
    h[(size_t)node * Hh + m]   = sigf(go) * tanhf(ct);
}

// ---------------------------------------------------------------------------
// One topological round. grid 148 x 640 thr (20 warps), overlapping
// 24-parent tiles. Thread = (q = t%160 col-quad, pg = t/160 parent-group).
// Output space 640 = [0,384) iou (gsum) | [384,512) s3 = U_f@gsum |
// [512,640) s4 = U_f@he2_a. Each thread uses ONE A-stream:
//   q<128: stream gsum, B rows 4q..4q+3 ; q>=128: stream he2_a, rows 4(q-32)..
// LDS per k per thread = 3 (B LDS.128 coalesced + A LDS.128 + LDS.64
// broadcast) — LSU dispatch 60 cyc/SMSP/k < FMA 120 -> FMA-bound.
// epi stores s3 raw at [512,640) and s4 raw at [384,512); epilogue:
// fa = s4, fb = s3 - s4.
// smem floats: As 16384 @0 | Bs 2*16*512 = 16384 @16384 (hs aliases Bs;
// epi[24*640] aliases As after GEMM)
// ---------------------------------------------------------------------------
#define RND_SMEMB (32768 * 4)

#define RLD(P, KK) \
    P##B  = *(const float4*)(Bq + (KK) * 512); \
    P##A4 = *(const float4*)(Ak + (KK) * 32); \
    P##A2 = *(const float2*)(Ak + (KK) * 32 + 4);

#define RFM(P) { \
    float2 a0 = make_float2(P##A4.x, P##A4.y); \
    float2 a1 = make_float2(P##A4.z, P##A4.w); \
    float2 bb; \
    bb = spl(P##B.x); \
    acc[0][0] = ffma2(bb, a0, acc[0][0]); \
    acc[0][1] = ffma2(bb, a1, acc[0][1]); \
    acc[0][2] = ffma2(bb, P##A2, acc[0][2]); \
    bb = spl(P##B.y); \
    acc[1][0] = ffma2(bb, a0, acc[1][0]); \
    acc[1][1] = ffma2(bb, a1, acc[1][1]); \
    acc[1][2] = ffma2(bb, P##A2, acc[1][2]); \
    bb = spl(P##B.z); \
    acc[2][0] = ffma2(bb, a0, acc[2][0]); \
    acc[2][1] = ffma2(bb, a1, acc[2][1]); \
    acc[2][2] = ffma2(bb, P##A2, acc[2][2]); \
    bb = spl(P##B.w); \
    acc[3][0] = ffma2(bb, a0, acc[3][0]); \
    acc[3][1] = ffma2(bb, a1, acc[3][1]); \
    acc[3][2] = ffma2(bb, P##A2, acc[3][2]); }

__global__ __launch_bounds__(640, 1) void k_round(int ri, float* __restrict__ h,
        const float* __restrict__ b_iou, const float* __restrict__ b_f,
        const int* __restrict__ edges_r, const float* __restrict__ labels) {
    extern __shared__ float sm[];
    float* As  = sm;            // 2*256*32 = 16384
    float* Bs  = sm + 16384;    // 2*16*512 = 16384
    float* hs  = Bs;            // staging alias (6336 <= 16384)
    float* epi = sm;            // alias after GEMM (15360 <= 16384)
    __shared__ int s_child[48], s_lab[48], s_par[24];

    int t  = threadIdx.x;
    int p0 = 2 * ((int)(blockIdx.x * 1488) / 147);     // even, <= 2976

    const int*   e_src   = edges_r + ri * 2 * EPRc;
    const int*   e_child = e_src + EPRc;
    const float* labp    = labels + ri * EPRc;

    if (t < 48) {
        int e = 2 * p0 + t;
        s_child[t] = e_child[e];
        s_lab[t]   = (labp[e] != 0.0f) ? 1 : 0;
    }
    if (t >= 64 && t < 88) {
        int pp = t - 64;
        s_par[pp] = e_src[2 * (p0 + pp)];
    }
    __syncthreads();

    // stage 48 child h-rows coalesced (1536 float4)
#pragma unroll
    for (int j = 0; j < 3; j++) {
        int f = t + 640 * j;
        if (f < 1536) {
            int e = f >> 5, qq = f & 31;
            *(float4*)&hs[e * 132 + 4 * qq] = *((const float4*)(h + (size_t)s_child[e] * Hh) + qq);
        }
    }
    __syncthreads();

    // build gsum (stream0) + he2_a (stream1), k-major stride 32, padded slots
#pragma unroll
    for (int rep = 0; rep < 2; rep++) {
        int f = t + 640 * rep;
        if (f < 768) {
            int p = f % 24, qq = f / 24;               // qq in [0,32)
            int s = (p / 6) * 8 + (p % 6);             // padded slot
            float4 vA = *(const float4*)&hs[(2 * p) * 132 + 4 * qq];
            float4 vB = *(const float4*)&hs[(2 * p + 1) * 132 + 4 * qq];
            float zA = (float)(1 - s_lab[2 * p]), oA = (float)s_lab[2 * p];
            float zB = (float)(1 - s_lab[2 * p + 1]), oB = (float)s_lab[2 * p + 1];
#pragma unroll
            for (int d = 0; d < 4; d++) {
                float hA = (d == 0) ? vA.x : (d == 1) ? vA.y : (d == 2) ? vA.z : vA.w;
                float hB = (d == 0) ? vB.x : (d == 1) ? vB.y : (d == 2) ? vB.z : vB.w;
                int klo = 4 * qq + d, khi = 128 + 4 * qq + d;
                float aLo = zA * hA, aHi = oA * hA;
                As[klo * 32 + s]         = aLo + zB * hB;   // gsum lo
                As[khi * 32 + s]         = aHi + oB * hB;   // gsum hi
                As[8192 + klo * 32 + s]  = aLo;             // he2_a lo
                As[8192 + khi * 32 + s]  = aHi;             // he2_a hi
            }
        }
    }
    __syncthreads();            // hs (Bs alias) dead from here

    // B chunk 0 (k=0..15): 8192 floats = 2048 float4
#pragma unroll
    for (int j = 0; j < 4; j++) {
        int f = t + 640 * j;
        if (f < 2048) {
            int ks = f >> 7, c4 = (f & 127) * 4;
            *(float4*)&Bs[ks * 512 + c4] = *(const float4*)&g_Ut[ks * 512 + c4];
        }
    }
    __syncthreads();

    int q  = t % 160;
    int pg = t / 160;                       // 0..3
    int rq4 = ((q < 128) ? q : (q - 32)) * 4;      // B row base
    const float* Ak0 = As + ((q < 128) ? 0 : 8192) + pg * 8;
    float2 acc[4][3];
#pragma unroll
    for (int cc = 0; cc < 4; cc++)
#pragma unroll
        for (int pr = 0; pr < 3; pr++) acc[cc][pr] = make_float2(0.f, 0.f);

#pragma unroll 1
    for (int c = 0; c < 16; c++) {                     // 16 chunks x 16 k
        float4 nb[4];
        if (c < 15) {
#pragma unroll
            for (int j = 0; j < 4; j++) {
                int f = t + 640 * j;
                if (f < 2048) {
                    int ks = f >> 7, c4 = (f & 127) * 4;
                    nb[j] = *(const float4*)&g_Ut[((c + 1) * 16 + ks) * 512 + c4];
                }
            }
        }
        const float* Bq = Bs + (c & 1) * 8192 + rq4;
        const float* Ak = Ak0 + c * 512;               // 16 k * 32 stride
        float4 XB, XA4; float2 XA2;
        float4 YB, YA4; float2 YA2;
        RLD(X, 0);
#pragma unroll
        for (int kp = 0; kp < 8; kp++) {
            RLD(Y, 2 * kp + 1);
            RFM(X);
            if (kp == 3 && c < 15) {                   // midpoint STS (safe)
                float* d = Bs + ((c + 1) & 1) * 8192;
#pragma unroll
                for (int j = 0; j < 4; j++) {
                    int f = t + 640 * j;
                    if (f < 2048) {
                        int ks = f >> 7, c4 = (f & 127) * 4;
                        *(float4*)&d[ks * 512 + c4] = nb[j];
                    }
                }
            }
            if (kp < 7) { RLD(X, 2 * kp + 2); }
            RFM(Y);
        }
        __syncthreads();
    }

    // scatter acc into epi: col co per quad-lane cc
    //  q<96: co = 4q+cc (iou) ; 96<=q<128: co = 4q+cc+128 (s3 raw at 512..640)
    //  q>=128: co = 4q+cc-128 (s4 raw at 384..512)
    int co0 = 4 * q + ((q < 96) ? 0 : (q < 128) ? 128 : -128);
#pragma unroll
    for (int cc = 0; cc < 4; cc++) {
        int co = co0 + cc;
#pragma unroll
        for (int pr = 0; pr < 3; pr++) {
            int p = pg * 6 + 2 * pr;
            epi[p * 640 + co]       = acc[cc][pr].x;
            epi[(p + 1) * 640 + co] = acc[cc][pr].y;
        }
    }
    __syncthreads();

    // epilogue: f gates, c accumulation, node_update (3072 items)
#pragma unroll
    for (int j = 0; j < 5; j++) {
        int idx = t + 640 * j;
        if (idx < 3072) {
            int pl = idx >> 7, m = idx & 127;
            int par = s_par[pl];
            int cA = s_child[2 * pl], cB = s_child[2 * pl + 1];
            const float* Cp = g_C + (size_t)par * NCc;
            float gi = Cp[m]       + epi[pl * 640 + m]       + b_iou[m];
            float go = Cp[128 + m] + epi[pl * 640 + 128 + m] + b_iou[128 + m];
            float gu = Cp[256 + m] + epi[pl * 640 + 256 + m] + b_iou[256 + m];
            float s4 = epi[pl * 640 + 384 + m];            // U_f @ he2_a
            float s3 = epi[pl * 640 + 512 + m];            // U_f @ gsum
            float fa = sigf(g_C[(size_t)cA * NCc + 384 + m] + s4 + b_f[m]);
            float fb = sigf(g_C[(size_t)cB * NCc + 384 + m] + (s3 - s4) + b_f[m]);
            float ca = g_c[(size_t)cA * Hh + m]; ca = fminf(fmaxf(ca, -1e14f), 1e14f);
            float cb = g_c[(size_t)cB * Hh + m]; cb = fminf(fmaxf(cb, -1e14f), 1e14f);
            float ct2 = sigf(gi) * tanhf(gu) + fa * ca + fb * cb;
            g_c[(size_t)par * Hh + m] = ct2;
            h[(size_t)par * Hh + m]   = sigf(go) * tanhf(ct2);
        }
    }
}

// ---------------------------------------------------------------------------
extern "C" void kernel_launch(void* const* d_in, const int* in_sizes, int n_in,
                              void* d_out, int out_size) {
    const float* x      = (const float*)d_in[0];
    const float* labels = (const float*)d_in[1];   // [15,6000,1]
    const float* W_iou  = (const float*)d_in[2];
    const float* W_f    = (const float*)d_in[3];
    const float* b_iou  = (const float*)d_in[4];
    const float* b_f    = (const float*)d_in[5];
    const float* U_iou  = (const float*)d_in[6];
    const float* U_f    = (const float*)d_in[7];
    const int*   edges  = (const int*)d_in[8];     // [15,2,6000]
    const int*   order0 = (const int*)d_in[9];
    float* h = (float*)d_out;                      // h lives directly in d_out

    cudaFuncSetAttribute(k_pre,   cudaFuncAttributeMaxDynamicSharedMemorySize, PRE_SMEMB);
    cudaFuncSetAttribute(k_round, cudaFuncAttributeMaxDynamicSharedMemorySize, RND_SMEMB);

    k_trans<<<768, 256>>>(U_iou, U_f, W_iou, W_f);
    k_pre<<<1500, 256, PRE_SMEMB>>>(x);
    k_round0<<<(NPRc * Hh + 255) / 256, 256>>>(h, order0, b_iou);
    for (int ri = 0; ri < 15; ri++)
        k_round<<<148, 640, RND_SMEMB>>>(ri, h, b_iou, b_f, edges, labels);
}

// round 13
// speedup vs baseline: 1.5770x; 1.5770x over previous
#include <cuda_runtime.h>
#include <math.h>

#define Hh   128
#define NPRc 3000
#define EPRc 6000
#define NTOT 48000
#define NCc  512     // C columns: [0,384) iou_x, [384,512) wf_x

// static scratch (no allocations allowed)
__device__ float g_C[(size_t)NTOT * NCc];   // 98.3 MB
__device__ float g_c[(size_t)NTOT * Hh];    // 24.6 MB
__device__ float g_Ut[256 * 512];           // U^T: [k][row]  (row<384: U_iou, else U_f)
__device__ float g_Wt[128 * 512];           // W^T: [k][row]  (row<384: W_iou, else W_f)

union F2U { float2 f; unsigned long long u; };
__device__ __forceinline__ float2 ffma2(float2 a, float2 b, float2 c) {
    F2U A, B, C2, D;
    A.f = a; B.f = b; C2.f = c;
    asm("fma.rn.f32x2 %0, %1, %2, %3;" : "=l"(D.u) : "l"(A.u), "l"(B.u), "l"(C2.u));
    return D.f;
}
__device__ __forceinline__ float2 spl(float b) { return make_float2(b, b); }
__device__ __forceinline__ float sigf(float x) { return 1.0f / (1.0f + expf(-x)); }

// ---------------------------------------------------------------------------
// One-shot weight transposes, merged (writes coalesced). grid 768.
// ---------------------------------------------------------------------------
__global__ __launch_bounds__(256) void k_trans(const float* __restrict__ U_iou,
                                               const float* __restrict__ U_f,
                                               const float* __restrict__ W_iou,
                                               const float* __restrict__ W_f) {
    int b = blockIdx.x;
    if (b < 512) {
        int idx = b * 256 + threadIdx.x;               // 131072
        int k = idx >> 9, row = idx & 511;
        g_Ut[idx] = (row < 384) ? U_iou[row * 256 + k] : U_f[(row - 384) * 256 + k];
    } else {
        int idx = (b - 512) * 256 + threadIdx.x;       // 65536
        int k = idx >> 9, row = idx & 511;
        g_Wt[idx] = (row < 384) ? W_iou[row * 128 + k] : W_f[(row - 384) * 128 + k];
    }
}

// ---------------------------------------------------------------------------
// k_pre: C[n][0:384] = x @ W_iou^T ; C[n][384:512] = x @ W_f^T
// Tiled GEMM: 32 rows x 512 cols per block, K=128. grid 1500, 2 blocks/SM.
// smem floats: A[128*36] @0 | Bs[2*8*512] @4608 | xs[32*132] @12800 = 17024
// ---------------------------------------------------------------------------
#define PRE_SMEMB (17024 * 4)

__global__ __launch_bounds__(256, 2) void k_pre(const float* __restrict__ x) {
    extern __shared__ float sm[];
    float* A  = sm;           // [k][row], stride 36
    float* Bs = sm + 4608;    // [buf][kk][512]
    float* xs = sm + 12800;   // [row][132]
    int t  = threadIdx.x;
    int r0 = blockIdx.x * 32;

#pragma unroll
    for (int j = 0; j < 4; j++) {                      // stage x coalesced
        int f = t + 256 * j, row = f >> 5, q = f & 31;
        *(float4*)&xs[row * 132 + 4 * q] = *((const float4*)(x + (size_t)(r0 + row) * 128) + q);
    }
    __syncthreads();
#pragma unroll
    for (int j = 0; j < 4; j++) {                      // transpose -> A[k][row]
        int f = t + 256 * j, row = f & 31, q = f >> 5;
        float4 v = *(const float4*)&xs[row * 132 + 4 * q];
        A[(4 * q + 0) * 36 + row] = v.x; A[(4 * q + 1) * 36 + row] = v.y;
        A[(4 * q + 2) * 36 + row] = v.z; A[(4 * q + 3) * 36 + row] = v.w;
    }
#pragma unroll
    for (int j = 0; j < 4; j++) {                      // B chunk 0 (k=0..7), coalesced
        int f = t + 256 * j, ks = f >> 7, c4 = (f & 127) * 4;
        *(float4*)&Bs[ks * 512 + c4] = *(const float4*)&g_Wt[ks * 512 + c4];
    }
    __syncthreads();

    int ct = t & 127;            // cols ct, 128+ct, 256+ct, 384+ct
    int rb = (t >> 7) * 16;      // 16 rows
    float2 acc[4][8];
#pragma unroll
    for (int cc = 0; cc < 4; cc++)
#pragma unroll
        for (int r = 0; r < 8; r++) acc[cc][r] = make_float2(0.f, 0.f);

#pragma unroll 1
    for (int c = 0; c < 16; c++) {                     // 16 chunks x 8 k
        float4 nb[4];
        if (c < 15) {
#pragma unroll
            for (int j = 0; j < 4; j++) {
                int f = t + 256 * j, ks = f >> 7, c4 = (f & 127) * 4;
                nb[j] = *(const float4*)&g_Wt[((c + 1) * 8 + ks) * 512 + c4];
            }
        }
        const float* Bb = Bs + (c & 1) * 4096;
#pragma unroll
        for (int kk = 0; kk < 8; kk++) {
            int kg = c * 8 + kk;
            float2 b0 = spl(Bb[kk * 512 + ct]);
            float2 b1 = spl(Bb[kk * 512 + 128 + ct]);
            float2 b2 = spl(Bb[kk * 512 + 256 + ct]);
            float2 b3 = spl(Bb[kk * 512 + 384 + ct]);
            const float* ap = A + kg * 36 + rb;
#pragma unroll
            for (int g4 = 0; g4 < 4; g4++) {
                float4 av = *(const float4*)(ap + 4 * g4);
                float2 p0 = make_float2(av.x, av.y), p1 = make_float2(av.z, av.w);
                acc[0][2*g4]   = ffma2(b0, p0, acc[0][2*g4]);
                acc[0][2*g4+1] = ffma2(b0, p1, acc[0][2*g4+1]);
                acc[1][2*g4]   = ffma2(b1, p0, acc[1][2*g4]);
                acc[1][2*g4+1] = ffma2(b1, p1, acc[1][2*g4+1]);
                acc[2][2*g4]   = ffma2(b2, p0, acc[2][2*g4]);
                acc[2][2*g4+1] = ffma2(b2, p1, acc[2][2*g4+1]);
                acc[3][2*g4]   = ffma2(b3, p0, acc[3][2*g4]);
                acc[3][2*g4+1] = ffma2(b3, p1, acc[3][2*g4+1]);
            }
        }
        if (c < 15) {
            float* d = Bs + ((c + 1) & 1) * 4096;
#pragma unroll
            for (int j = 0; j < 4; j++) {
                int f = t + 256 * j, ks = f >> 7, c4 = (f & 127) * 4;
                *(float4*)&d[ks * 512 + c4] = nb[j];
            }
            __syncthreads();
        }
    }
#pragma unroll
    for (int cc = 0; cc < 4; cc++) {                   // grid*32 == 48000, no guard
        int col = ct + 128 * cc;
#pragma unroll
        for (int r = 0; r < 8; r++) {
            int row = r0 + rb + 2 * r;
            g_C[(size_t)row * NCc + col]       = acc[cc][r].x;
            g_C[(size_t)(row + 1) * NCc + col] = acc[cc][r].y;
        }
    }
}

// ---------------------------------------------------------------------------
// Round 0: leaves. iou_mid = 0, c = 0.
// ---------------------------------------------------------------------------
__global__ __launch_bounds__(256) void k_round0(float* __restrict__ h,
                                                const int* __restrict__ order0,
                                                const float* __restrict__ b_iou) {
    int idx = blockIdx.x * 256 + threadIdx.x;
    if (idx >= NPRc * Hh) return;
    int j = idx >> 7, m = idx & 127;
    int node = order0[j];
    const float* Cp = g_C + (size_t)node * NCc;
    float gi = Cp[m]       + b_iou[m];
    float go = Cp[128 + m] + b_iou[128 + m];
    float gu = Cp[256 + m] + b_iou[256 + m];
    float ct = sigf(gi) * tanhf(gu);
    g_c[(size_t)node * Hh + m] = ct;
    h[(size_t)node * Hh + m]   = sigf(go) * tanhf(ct);
}

// ---------------------------------------------------------------------------
// One topological round. grid 148 x 640 thr (20 warps), overlapping
// 24-parent tiles. Thread = (q = t%160 col-quad, pg = t/160 parent-group).
// Output space 640 = [0,384) iou (gsum) | [384,512) s3 = U_f@gsum |
// [512,640) s4 = U_f@he2_a. Each thread uses ONE A-stream:
//   q<128: stream gsum, B rows 4q..4q+3 ; q>=128: stream he2_a, rows 4(q-32)..
// LDS per k per thread = 3 (B LDS.128 coalesced + A LDS.128 + LDS.64
// broadcast) — LSU dispatch 60 cyc/SMSP/k < FMA 120 -> FMA-bound.
// epi stores s3 raw at [512,640) and s4 raw at [384,512); epilogue:
// fa = s4, fb = s3 - s4.
// smem floats: As 16384 @0 | Bs 2*16*512 = 16384 @16384 (hs aliases Bs;
// epi[24*640] aliases As after GEMM)
// ---------------------------------------------------------------------------
#define RND_SMEMB (32768 * 4)

#define RLD(P, KK) \
    P##B  = *(const float4*)(Bq + (KK) * 512); \
    P##A4 = *(const float4*)(Ak + (KK) * 32); \
    P##A2 = *(const float2*)(Ak + (KK) * 32 + 4);

#define RFM(P) { \
    float2 a0 = make_float2(P##A4.x, P##A4.y); \
    float2 a1 = make_float2(P##A4.z, P##A4.w); \
    float2 bb; \
    bb = spl(P##B.x); \
    acc[0][0] = ffma2(bb, a0, acc[0][0]); \
    acc[0][1] = ffma2(bb, a1, acc[0][1]); \
    acc[0][2] = ffma2(bb, P##A2, acc[0][2]); \
    bb = spl(P##B.y); \
    acc[1][0] = ffma2(bb, a0, acc[1][0]); \
    acc[1][1] = ffma2(bb, a1, acc[1][1]); \
    acc[1][2] = ffma2(bb, P##A2, acc[1][2]); \
    bb = spl(P##B.z); \
    acc[2][0] = ffma2(bb, a0, acc[2][0]); \
    acc[2][1] = ffma2(bb, a1, acc[2][1]); \
    acc[2][2] = ffma2(bb, P##A2, acc[2][2]); \
    bb = spl(P##B.w); \
    acc[3][0] = ffma2(bb, a0, acc[3][0]); \
    acc[3][1] = ffma2(bb, a1, acc[3][1]); \
    acc[3][2] = ffma2(bb, P##A2, acc[3][2]); }

__global__ __launch_bounds__(640, 1) void k_round(int ri, float* __restrict__ h,
        const float* __restrict__ b_iou, const float* __restrict__ b_f,
        const int* __restrict__ edges_r, const float* __restrict__ labels) {
    extern __shared__ float sm[];
    float* As  = sm;            // 2*256*32 = 16384
    float* Bs  = sm + 16384;    // 2*16*512 = 16384
    float* hs  = Bs;            // staging alias (6336 <= 16384)
    float* epi = sm;            // alias after GEMM (15360 <= 16384)
    __shared__ int s_child[48], s_lab[48], s_par[24];

    int t  = threadIdx.x;
    int p0 = 2 * ((int)(blockIdx.x * 1488) / 147);     // even, <= 2976

    const int*   e_src   = edges_r + ri * 2 * EPRc;
    const int*   e_child = e_src + EPRc;
    const float* labp    = labels + ri * EPRc;

    if (t < 48) {
        int e = 2 * p0 + t;
        s_child[t] = e_child[e];
        s_lab[t]   = (labp[e] != 0.0f) ? 1 : 0;
    }
    if (t >= 64 && t < 88) {
        int pp = t - 64;
        s_par[pp] = e_src[2 * (p0 + pp)];
    }
    __syncthreads();

    // stage 48 child h-rows coalesced (1536 float4)
#pragma unroll
    for (int j = 0; j < 3; j++) {
        int f = t + 640 * j;
        if (f < 1536) {
            int e = f >> 5, qq = f & 31;
            *(float4*)&hs[e * 132 + 4 * qq] = *((const float4*)(h + (size_t)s_child[e] * Hh) + qq);
        }
    }
    __syncthreads();

    // build gsum (stream0) + he2_a (stream1), k-major stride 32, padded slots
#pragma unroll
    for (int rep = 0; rep < 2; rep++) {
        int f = t + 640 * rep;
        if (f < 768) {
            int p = f % 24, qq = f / 24;               // qq in [0,32)
            int s = (p / 6) * 8 + (p % 6);             // padded slot
            float4 vA = *(const float4*)&hs[(2 * p) * 132 + 4 * qq];
            float4 vB = *(const float4*)&hs[(2 * p + 1) * 132 + 4 * qq];
            float zA = (float)(1 - s_lab[2 * p]), oA = (float)s_lab[2 * p];
            float zB = (float)(1 - s_lab[2 * p + 1]), oB = (float)s_lab[2 * p + 1];
#pragma unroll
            for (int d = 0; d < 4; d++) {
                float hA = (d == 0) ? vA.x : (d == 1) ? vA.y : (d == 2) ? vA.z : vA.w;
                float hB = (d == 0) ? vB.x : (d == 1) ? vB.y : (d == 2) ? vB.z : vB.w;
                int klo = 4 * qq + d, khi = 128 + 4 * qq + d;
                float aLo = zA * hA, aHi = oA * hA;
                As[klo * 32 + s]         = aLo + zB * hB;   // gsum lo
                As[khi * 32 + s]         = aHi + oB * hB;   // gsum hi
                As[8192 + klo * 32 + s]  = aLo;             // he2_a lo
                As[8192 + khi * 32 + s]  = aHi;             // he2_a hi
            }
        }
    }
    __syncthreads();            // hs (Bs alias) dead from here

    // B chunk 0 (k=0..15): 8192 floats = 2048 float4
#pragma unroll
    for (int j = 0; j < 4; j++) {
        int f = t + 640 * j;
        if (f < 2048) {
            int ks = f >> 7, c4 = (f & 127) * 4;
            *(float4*)&Bs[ks * 512 + c4] = *(const float4*)&g_Ut[ks * 512 + c4];
        }
    }
    __syncthreads();

    int q  = t % 160;
    int pg = t / 160;                       // 0..3
    int rq4 = ((q < 128) ? q : (q - 32)) * 4;      // B row base
    const float* Ak0 = As + ((q < 128) ? 0 : 8192) + pg * 8;
    float2 acc[4][3];
#pragma unroll
    for (int cc = 0; cc < 4; cc++)
#pragma unroll
        for (int pr = 0; pr < 3; pr++) acc[cc][pr] = make_float2(0.f, 0.f);

#pragma unroll 1
    for (int c = 0; c < 16; c++) {                     // 16 chunks x 16 k
        float4 nb[4];
        if (c < 15) {
#pragma unroll
            for (int j = 0; j < 4; j++) {
                int f = t + 640 * j;
                if (f < 2048) {
                    int ks = f >> 7, c4 = (f & 127) * 4;
                    nb[j] = *(const float4*)&g_Ut[((c + 1) * 16 + ks) * 512 + c4];
                }
            }
        }
        const float* Bq = Bs + (c & 1) * 8192 + rq4;
        const float* Ak = Ak0 + c * 512;               // 16 k * 32 stride
        float4 XB, XA4; float2 XA2;
        float4 YB, YA4; float2 YA2;
        RLD(X, 0);
#pragma unroll
        for (int kp = 0; kp < 8; kp++) {
            RLD(Y, 2 * kp + 1);
            RFM(X);
            if (kp == 3 && c < 15) {                   // midpoint STS (safe)
                float* d = Bs + ((c + 1) & 1) * 8192;
#pragma unroll
                for (int j = 0; j < 4; j++) {
                    int f = t + 640 * j;
                    if (f < 2048) {
                        int ks = f >> 7, c4 = (f & 127) * 4;
                        *(float4*)&d[ks * 512 + c4] = nb[j];
                    }
                }
            }
            if (kp < 7) { RLD(X, 2 * kp + 2); }
            RFM(Y);
        }
        __syncthreads();
    }

    // scatter acc into epi: col co per quad-lane cc
    //  q<96: co = 4q+cc (iou) ; 96<=q<128: co = 4q+cc+128 (s3 raw at 512..640)
    //  q>=128: co = 4q+cc-128 (s4 raw at 384..512)
    int co0 = 4 * q + ((q < 96) ? 0 : (q < 128) ? 128 : -128);
#pragma unroll
    for (int cc = 0; cc < 4; cc++) {
        int co = co0 + cc;
#pragma unroll
        for (int pr = 0; pr < 3; pr++) {
            int p = pg * 6 + 2 * pr;
            epi[p * 640 + co]       = acc[cc][pr].x;
            epi[(p + 1) * 640 + co] = acc[cc][pr].y;
        }
    }
    __syncthreads();

    // epilogue: f gates, c accumulation, node_update (3072 items)
#pragma unroll
    for (int j = 0; j < 5; j++) {
        int idx = t + 640 * j;
        if (idx < 3072) {
            int pl = idx >> 7, m = idx & 127;
            int par = s_par[pl];
            int cA = s_child[2 * pl], cB = s_child[2 * pl + 1];
            const float* Cp = g_C + (size_t)par * NCc;
            float gi = Cp[m]       + epi[pl * 640 + m]       + b_iou[m];
            float go = Cp[128 + m] + epi[pl * 640 + 128 + m] + b_iou[128 + m];
            float gu = Cp[256 + m] + epi[pl * 640 + 256 + m] + b_iou[256 + m];
            float s4 = epi[pl * 640 + 384 + m];            // U_f @ he2_a
            float s3 = epi[pl * 640 + 512 + m];            // U_f @ gsum
            float fa = sigf(g_C[(size_t)cA * NCc + 384 + m] + s4 + b_f[m]);
            float fb = sigf(g_C[(size_t)cB * NCc + 384 + m] + (s3 - s4) + b_f[m]);
            float ca = g_c[(size_t)cA * Hh + m]; ca = fminf(fmaxf(ca, -1e14f), 1e14f);
            float cb = g_c[(size_t)cB * Hh + m]; cb = fminf(fmaxf(cb, -1e14f), 1e14f);
            float ct2 = sigf(gi) * tanhf(gu) + fa * ca + fb * cb;
            g_c[(size_t)par * Hh + m] = ct2;
            h[(size_t)par * Hh + m]   = sigf(go) * tanhf(ct2);
        }
    }
}

// ---------------------------------------------------------------------------
extern "C" void kernel_launch(void* const* d_in, const int* in_sizes, int n_in,
                              void* d_out, int out_size) {
    const float* x      = (const float*)d_in[0];
    const float* labels = (const float*)d_in[1];   // [15,6000,1]
    const float* W_iou  = (const float*)d_in[2];
    const float* W_f    = (const float*)d_in[3];
    const float* b_iou  = (const float*)d_in[4];
    const float* b_f    = (const float*)d_in[5];
    const float* U_iou  = (const float*)d_in[6];
    const float* U_f    = (const float*)d_in[7];
    const int*   edges  = (const int*)d_in[8];     // [15,2,6000]
    const int*   order0 = (const int*)d_in[9];
    float* h = (float*)d_out;                      // h lives directly in d_out

    cudaFuncSetAttribute(k_pre,   cudaFuncAttributeMaxDynamicSharedMemorySize, PRE_SMEMB);
    cudaFuncSetAttribute(k_round, cudaFuncAttributeMaxDynamicSharedMemorySize, RND_SMEMB);

    k_trans<<<768, 256>>>(U_iou, U_f, W_iou, W_f);
    k_pre<<<1500, 256, PRE_SMEMB>>>(x);
    k_round0<<<(NPRc * Hh + 255) / 256, 256>>>(h, order0, b_iou);
    for (int ri = 0; ri < 15; ri++)
        k_round<<<148, 640, RND_SMEMB>>>(ri, h, b_iou, b_f, edges, labels);
}